// round 3
// baseline (speedup 1.0000x reference)
#include <cuda_runtime.h>
#include <math.h>

#define NN   50000
#define EE   800000
#define HD   256
#define LL   4
#define H2   512
#define DOUT 2
#define BNEPS 1e-5f

// ---------------- scratch (no allocations allowed) ----------------
__device__ float g_buf0[(size_t)NN * HD];
__device__ float g_buf1[(size_t)NN * HD];
__device__ float g_buf2[(size_t)NN * HD];
__device__ float g_mlp [(size_t)NN * H2];
__device__ float g_deg [NN];
__device__ float g_bnsum[2 * HD];   // [0:256) sum, [256:512) sumsq
__device__ float g_bnsc [HD];       // gamma * rstd
__device__ float g_bnsh [HD];       // beta - mu * gamma * rstd

// ---------------- small utility kernels ----------------
__global__ void k_zero4(float4* p, int n4) {
    int i = blockIdx.x * blockDim.x + threadIdx.x;
    if (i < n4) p[i] = make_float4(0.f, 0.f, 0.f, 0.f);
}

__global__ void k_deg_count(const int* __restrict__ dst, float* __restrict__ deg, int e) {
    int i = blockIdx.x * blockDim.x + threadIdx.x;
    if (i < e) atomicAdd(&deg[dst[i]], 1.0f);
}

__global__ void k_deg_inv(float* deg, int n) {
    int i = blockIdx.x * blockDim.x + threadIdx.x;
    if (i < n) deg[i] = 1.0f / fmaxf(deg[i], 1.0f);
}

// agg[dst] += h[src], one float4 chunk per thread, vectorized L2 reduction
__global__ void k_scatter(const float4* __restrict__ h, const int* __restrict__ src,
                          const int* __restrict__ dst, float* __restrict__ agg) {
    long long i = (long long)blockIdx.x * blockDim.x + threadIdx.x;
    long long total = (long long)EE * 64;
    if (i >= total) return;
    int e = (int)(i >> 6);
    int g = (int)(i & 63);
    int s = src[e], d = dst[e];
    float4 v = h[(size_t)s * 64 + g];
    float* o = agg + (size_t)d * HD + g * 4;
    asm volatile("red.global.add.v4.f32 [%0], {%1, %2, %3, %4};"
                 :: "l"(o), "f"(v.x), "f"(v.y), "f"(v.z), "f"(v.w) : "memory");
}

// column sums / sumsq over [NN, 256], chunked rows + block-level atomics
__global__ void k_bn_reduce(const float* __restrict__ x, float* __restrict__ sums) {
    int col = threadIdx.x;               // 0..255
    int r0 = blockIdx.x * 128;
    int rend = min(r0 + 128, NN);
    float s = 0.f, q = 0.f;
    for (int r = r0; r < rend; r++) {
        float v = x[(size_t)r * HD + col];
        s += v;
        q += v * v;
    }
    atomicAdd(&sums[col], s);
    atomicAdd(&sums[HD + col], q);
}

__global__ void k_bn_final(const float* __restrict__ sums, const float* __restrict__ g,
                           const float* __restrict__ b, float* __restrict__ sc,
                           float* __restrict__ sh) {
    int c = threadIdx.x;
    float mu  = sums[c] * (1.0f / NN);
    float var = sums[HD + c] * (1.0f / NN) - mu * mu;
    float rstd = rsqrtf(var + BNEPS);
    float s = g[c] * rstd;
    sc[c] = s;
    sh[c] = b[c] - mu * s;
}

// ---------------- generic NT GEMM: C = A*W^T (+ A2*W2^T) + bias, epilogues ----------------
// EPI 0: relu(acc + bias)
// EPI 1: acc + bias
// EPI 2: acc + bias + relu(aux * bn_sc + bn_sh)   (skip + fused BN+ReLU)
// Optional rowscale rs[]: A rows (pass 0 only) are multiplied by rs[row] on load.
template <int EPI, bool DUAL, bool RS>
__global__ void __launch_bounds__(256, 2)
k_gemm(const float* __restrict__ A, const float* __restrict__ W,
       const float* __restrict__ A2, const float* __restrict__ W2,
       const float* __restrict__ bias,
       const float* __restrict__ bn_sc, const float* __restrict__ bn_sh,
       const float* __restrict__ aux, const float* __restrict__ rs,
       float* __restrict__ C, int M, int Nc, int K) {
    constexpr int BM = 128, BN = 128, BK = 16;
    __shared__ float As[BK][BM + 4];
    __shared__ float Ws[BK][BN + 4];

    const int tid = threadIdx.x;
    const int tx = tid & 15;        // col group: 8 cols
    const int ty = tid >> 4;        // row group: 8 rows
    const int m0 = blockIdx.y * BM;
    const int n0 = blockIdx.x * BN;
    const int lr = tid >> 2;        // 0..63
    const int lc = (tid & 3) * 4;   // 0,4,8,12

    const int itersPerPass = K / BK;
    const int totalIters = (DUAL ? 2 : 1) * itersPerPass;

    float acc[8][8];
#pragma unroll
    for (int i = 0; i < 8; i++)
#pragma unroll
        for (int j = 0; j < 8; j++) acc[i][j] = 0.f;

    float4 ra[2], rw[2];

    // stage loader: iteration it -> registers
    auto stage = [&](int it) {
        int pass = DUAL ? (it / itersPerPass) : 0;
        int k0 = (it - pass * itersPerPass) * BK;
        const float* Ap = pass ? A2 : A;
        const float* Wp = pass ? W2 : W;
#pragma unroll
        for (int half = 0; half < 2; half++) {
            int row = m0 + half * 64 + lr;
            float4 av = make_float4(0.f, 0.f, 0.f, 0.f);
            if (row < M) {
                av = *(const float4*)&Ap[(size_t)row * K + k0 + lc];
                if (RS && pass == 0) {
                    float s = rs[row];
                    av.x *= s; av.y *= s; av.z *= s; av.w *= s;
                }
            }
            ra[half] = av;
            rw[half] = *(const float4*)&Wp[(size_t)(n0 + half * 64 + lr) * K + k0 + lc];
        }
    };

    stage(0);
    for (int it = 0; it < totalIters; ++it) {
        // commit staged tile to smem
#pragma unroll
        for (int half = 0; half < 2; half++) {
            As[lc + 0][half * 64 + lr] = ra[half].x;
            As[lc + 1][half * 64 + lr] = ra[half].y;
            As[lc + 2][half * 64 + lr] = ra[half].z;
            As[lc + 3][half * 64 + lr] = ra[half].w;
            Ws[lc + 0][half * 64 + lr] = rw[half].x;
            Ws[lc + 1][half * 64 + lr] = rw[half].y;
            Ws[lc + 2][half * 64 + lr] = rw[half].z;
            Ws[lc + 3][half * 64 + lr] = rw[half].w;
        }
        __syncthreads();
        if (it + 1 < totalIters) stage(it + 1);   // prefetch next into regs
#pragma unroll
        for (int k = 0; k < BK; k++) {
            float4 a0 = *(const float4*)&As[k][ty * 8 + 0];
            float4 a1 = *(const float4*)&As[k][ty * 8 + 4];
            float4 b0 = *(const float4*)&Ws[k][tx * 8 + 0];
            float4 b1 = *(const float4*)&Ws[k][tx * 8 + 4];
            float ar[8] = {a0.x, a0.y, a0.z, a0.w, a1.x, a1.y, a1.z, a1.w};
            float br[8] = {b0.x, b0.y, b0.z, b0.w, b1.x, b1.y, b1.z, b1.w};
#pragma unroll
            for (int i = 0; i < 8; i++)
#pragma unroll
                for (int j = 0; j < 8; j++) acc[i][j] = fmaf(ar[i], br[j], acc[i][j]);
        }
        __syncthreads();
    }

    // epilogue (vectorized stores)
#pragma unroll
    for (int i = 0; i < 8; i++) {
        int m = m0 + ty * 8 + i;
        if (m >= M) continue;
#pragma unroll
        for (int jj = 0; jj < 2; jj++) {
            int n = n0 + tx * 8 + jj * 4;
            float4 v;
            float* vp = &v.x;
            float4 xx;
            if (EPI == 2) xx = *(const float4*)&aux[(size_t)m * Nc + n];
            const float* xp = &xx.x;
#pragma unroll
            for (int t = 0; t < 4; t++) {
                float val = acc[i][jj * 4 + t] + bias[n + t];
                if (EPI == 0) val = fmaxf(val, 0.f);
                if (EPI == 2) val += fmaxf(fmaf(xp[t], bn_sc[n + t], bn_sh[n + t]), 0.f);
                vp[t] = val;
            }
            *(float4*)&C[(size_t)m * Nc + n] = v;
        }
    }
}

// ---------------- final head: [M,256] @ [2,256]^T + b, log_softmax ----------------
__global__ void k_out_lsm(const float* __restrict__ h, const float* __restrict__ w,
                          const float* __restrict__ b, float* __restrict__ out, int M) {
    int row = blockIdx.x * blockDim.y + threadIdx.y;
    if (row >= M) return;
    int lane = threadIdx.x;
    const float* hr = h + (size_t)row * HD;
    float s0 = 0.f, s1 = 0.f;
    for (int k = lane; k < HD; k += 32) {
        float v = hr[k];
        s0 = fmaf(v, w[k], s0);
        s1 = fmaf(v, w[HD + k], s1);
    }
#pragma unroll
    for (int o = 16; o; o >>= 1) {
        s0 += __shfl_down_sync(0xffffffffu, s0, o);
        s1 += __shfl_down_sync(0xffffffffu, s1, o);
    }
    if (lane == 0) {
        float z0 = s0 + b[0], z1 = s1 + b[1];
        float mx = fmaxf(z0, z1);
        float lse = mx + logf(expf(z0 - mx) + expf(z1 - mx));
        out[(size_t)row * 2 + 0] = z0 - lse;
        out[(size_t)row * 2 + 1] = z1 - lse;
    }
}

// ---------------- launch ----------------
extern "C" void kernel_launch(void* const* d_in, const int* in_sizes, int n_in,
                              void* d_out, int out_size) {
    const float* x     = (const float*)d_in[0];
    const int*   ei    = (const int*)  d_in[1];
    const float* in_w  = (const float*)d_in[2];
    const float* in_b  = (const float*)d_in[3];
    const float* cwl   = (const float*)d_in[4];
    const float* cbl   = (const float*)d_in[5];
    const float* cwr   = (const float*)d_in[6];
    const float* bng   = (const float*)d_in[7];
    const float* bnb   = (const float*)d_in[8];
    const float* skw   = (const float*)d_in[9];
    const float* skb   = (const float*)d_in[10];
    const float* mw1   = (const float*)d_in[11];
    const float* mb1   = (const float*)d_in[12];
    const float* mw2   = (const float*)d_in[13];
    const float* mb2   = (const float*)d_in[14];
    const float* outw  = (const float*)d_in[15];
    const float* outb  = (const float*)d_in[16];
    float* out = (float*)d_out;

    const int* src = ei;
    const int* dst = ei + EE;

    float *b0, *b1, *b2, *bt, *deg, *bns, *bsc, *bsh;
    cudaGetSymbolAddress((void**)&b0,  g_buf0);
    cudaGetSymbolAddress((void**)&b1,  g_buf1);
    cudaGetSymbolAddress((void**)&b2,  g_buf2);
    cudaGetSymbolAddress((void**)&bt,  g_mlp);
    cudaGetSymbolAddress((void**)&deg, g_deg);
    cudaGetSymbolAddress((void**)&bns, g_bnsum);
    cudaGetSymbolAddress((void**)&bsc, g_bnsc);
    cudaGetSymbolAddress((void**)&bsh, g_bnsh);

    const int TPB = 256;
    const long long feat4 = (long long)NN * 64;
    const int featBlocks = (int)((feat4 + TPB - 1) / TPB);
    const long long scat = (long long)EE * 64;
    const int scatBlocks = (int)((scat + TPB - 1) / TPB);
    const int bnChunks = (NN + 127) / 128;

    // degrees -> inverse degrees
    k_zero4<<<(NN / 4 + TPB - 1) / TPB, TPB>>>((float4*)deg, NN / 4);
    k_deg_count<<<(EE + TPB - 1) / TPB, TPB>>>(dst, deg, EE);
    k_deg_inv<<<(NN + TPB - 1) / TPB, TPB>>>(deg, NN);

    dim3 g256(HD / 128, (NN + 127) / 128);
    dim3 g512(H2 / 128, (NN + 127) / 128);

    // input projection + relu  -> b0
    k_gemm<0, false, false><<<g256, TPB>>>(x, in_w, nullptr, nullptr, in_b,
                                           nullptr, nullptr, nullptr, nullptr,
                                           b0, NN, HD, HD);

    float* bufs[3] = {b0, b1, b2};
    int hi = 0;
    for (int l = 0; l < LL; l++) {
        float* h   = bufs[hi];
        float* agg = bufs[(hi + 1) % 3];
        float* cv  = bufs[(hi + 2) % 3];

        k_zero4<<<featBlocks, TPB>>>((float4*)agg, (int)feat4);
        k_scatter<<<scatBlocks, TPB>>>((const float4*)h, src, dst, agg);

        // cv = (agg * invdeg) @ wl^T + h @ wr^T + bl   (deg-normalization fused into A-load)
        k_gemm<1, true, true><<<g256, TPB>>>(agg, cwl + (size_t)l * HD * HD,
                                             h,   cwr + (size_t)l * HD * HD,
                                             cbl + (size_t)l * HD,
                                             nullptr, nullptr, nullptr, deg,
                                             cv, NN, HD, HD);

        // batch-norm statistics on cv
        k_zero4<<<1, 128>>>((float4*)bns, 128);
        k_bn_reduce<<<bnChunks, HD>>>(cv, bns);
        k_bn_final<<<1, HD>>>(bns, bng + (size_t)l * HD, bnb + (size_t)l * HD, bsc, bsh);

        // cv = h @ skip_w^T + skip_b + relu(bn(cv))   (in-place aux read is per-element safe)
        k_gemm<2, false, false><<<g256, TPB>>>(h, skw + (size_t)l * HD * HD, nullptr, nullptr,
                                               skb + (size_t)l * HD, bsc, bsh, cv, nullptr,
                                               cv, NN, HD, HD);
        hi = (hi + 2) % 3;
    }

    float* h  = bufs[hi];
    float* h2 = bufs[(hi + 1) % 3];

    // MLP
    k_gemm<0, false, false><<<g512, TPB>>>(h, mw1, nullptr, nullptr, mb1,
                                           nullptr, nullptr, nullptr, nullptr,
                                           bt, NN, H2, HD);
    k_gemm<1, false, false><<<g256, TPB>>>(bt, mw2, nullptr, nullptr, mb2,
                                           nullptr, nullptr, nullptr, nullptr,
                                           h2, NN, HD, H2);

    // output head + log_softmax
    dim3 ob(32, 8);
    k_out_lsm<<<(NN + 7) / 8, ob>>>(h2, outw, outb, out, NN);
}

// round 8
// speedup vs baseline: 1.8318x; 1.8318x over previous
#include <cuda_runtime.h>
#include <cuda_bf16.h>
#include <math.h>
#include <stdint.h>

#define NN   50000
#define EE   800000
#define HD   256
#define LL   4
#define H2   512
#define BNEPS 1e-5f
#define NPAD 50048   // 391*128

// ---------------- scratch (no allocations allowed) ----------------
__device__ float g_buf0[(size_t)NN * HD];
__device__ float g_buf1[(size_t)NN * HD];
__device__ float g_buf2[(size_t)NN * HD];
__device__ float g_mlp [(size_t)NN * H2];
__device__ float g_deg [NN];
__device__ float g_bnsum[2 * HD];
__device__ float g_bnsc [HD];
__device__ float g_bnsh [HD];

// bf16 hi/lo activation planes (pad rows stay zero: zero-init, never written)
__device__ __align__(16) __nv_bfloat16 g_p0h[(size_t)NPAD * HD];
__device__ __align__(16) __nv_bfloat16 g_p0l[(size_t)NPAD * HD];
__device__ __align__(16) __nv_bfloat16 g_p1h[(size_t)NPAD * HD];
__device__ __align__(16) __nv_bfloat16 g_p1l[(size_t)NPAD * HD];
__device__ __align__(16) __nv_bfloat16 g_bth[(size_t)NPAD * H2];
__device__ __align__(16) __nv_bfloat16 g_btl[(size_t)NPAD * H2];

// weight planes, concatenated
#define WOFF_IN  0
#define WOFF_CWL 65536
#define WOFF_CWR 327680
#define WOFF_SKW 589824
#define WOFF_MW1 851968
#define WOFF_MW2 983040
#define WTOT     1114112
__device__ __align__(16) __nv_bfloat16 g_wph[WTOT];
__device__ __align__(16) __nv_bfloat16 g_wpl[WTOT];

// ---------------- PTX helpers ----------------
__device__ __forceinline__ uint32_t smem_u32(const void* p) {
    uint32_t a;
    asm("{ .reg .u64 t; cvta.to.shared.u64 t, %1; cvt.u32.u64 %0, t; }" : "=r"(a) : "l"(p));
    return a;
}
#define CP_ASYNC16(s, g) \
    asm volatile("cp.async.cg.shared.global [%0], [%1], 16;" :: "r"(s), "l"(g) : "memory")
#define CP_COMMIT() asm volatile("cp.async.commit_group;" ::: "memory")
#define CP_WAIT(N)  asm volatile("cp.async.wait_group %0;" :: "n"(N) : "memory")

#define LDMATRIX_X4(r0, r1, r2, r3, a) \
    asm volatile("ldmatrix.sync.aligned.m8n8.x4.shared.b16 {%0,%1,%2,%3}, [%4];" \
                 : "=r"(r0), "=r"(r1), "=r"(r2), "=r"(r3) : "r"(a))

#define MMA_BF16(c, a, b) \
    asm volatile("mma.sync.aligned.m16n8k16.row.col.f32.bf16.bf16.f32 " \
                 "{%0,%1,%2,%3}, {%4,%5,%6,%7}, {%8,%9}, {%0,%1,%2,%3};" \
                 : "+f"((c)[0]), "+f"((c)[1]), "+f"((c)[2]), "+f"((c)[3]) \
                 : "r"((a)[0]), "r"((a)[1]), "r"((a)[2]), "r"((a)[3]), "r"((b)[0]), "r"((b)[1]))

// fp32x4 -> bf16 hi/lo (Dekker split; residual exact in fp32)
__device__ __forceinline__ void split4(float4 f, uint2& h, uint2& l) {
    asm("cvt.rn.bf16x2.f32 %0, %1, %2;" : "=r"(h.x) : "f"(f.y), "f"(f.x));
    asm("cvt.rn.bf16x2.f32 %0, %1, %2;" : "=r"(h.y) : "f"(f.w), "f"(f.z));
    float a0 = __uint_as_float(h.x << 16), a1 = __uint_as_float(h.x & 0xffff0000u);
    float a2 = __uint_as_float(h.y << 16), a3 = __uint_as_float(h.y & 0xffff0000u);
    float r0 = f.x - a0, r1 = f.y - a1, r2 = f.z - a2, r3 = f.w - a3;
    asm("cvt.rn.bf16x2.f32 %0, %1, %2;" : "=r"(l.x) : "f"(r1), "f"(r0));
    asm("cvt.rn.bf16x2.f32 %0, %1, %2;" : "=r"(l.y) : "f"(r3), "f"(r2));
}
__device__ __forceinline__ void split2(float2 f, uint32_t& h, uint32_t& l) {
    asm("cvt.rn.bf16x2.f32 %0, %1, %2;" : "=r"(h) : "f"(f.y), "f"(f.x));
    float a0 = __uint_as_float(h << 16), a1 = __uint_as_float(h & 0xffff0000u);
    float r0 = f.x - a0, r1 = f.y - a1;
    asm("cvt.rn.bf16x2.f32 %0, %1, %2;" : "=r"(l) : "f"(r1), "f"(r0));
}

// ---------------- utility kernels ----------------
__global__ void k_zero4(float4* p, int n4) {
    int i = blockIdx.x * blockDim.x + threadIdx.x;
    if (i < n4) p[i] = make_float4(0.f, 0.f, 0.f, 0.f);
}
__global__ void k_deg_count(const int* __restrict__ dst, float* __restrict__ deg, int e) {
    int i = blockIdx.x * blockDim.x + threadIdx.x;
    if (i < e) atomicAdd(&deg[dst[i]], 1.0f);
}
__global__ void k_deg_inv(float* deg, int n) {
    int i = blockIdx.x * blockDim.x + threadIdx.x;
    if (i < n) deg[i] = 1.0f / fmaxf(deg[i], 1.0f);
}
__global__ void k_scatter(const float4* __restrict__ h, const int* __restrict__ src,
                          const int* __restrict__ dst, float* __restrict__ agg) {
    long long i = (long long)blockIdx.x * blockDim.x + threadIdx.x;
    long long total = (long long)EE * 64;
    if (i >= total) return;
    int e = (int)(i >> 6);
    int g = (int)(i & 63);
    int s = src[e], d = dst[e];
    float4 v = h[(size_t)s * 64 + g];
    float* o = agg + (size_t)d * HD + g * 4;
    asm volatile("red.global.add.v4.f32 [%0], {%1, %2, %3, %4};"
                 :: "l"(o), "f"(v.x), "f"(v.y), "f"(v.z), "f"(v.w) : "memory");
}
__global__ void k_bn_reduce(const float* __restrict__ x, float* __restrict__ sums) {
    int col = threadIdx.x;
    int r0 = blockIdx.x * 128;
    int rend = min(r0 + 128, NN);
    float s = 0.f, q = 0.f;
    for (int r = r0; r < rend; r++) {
        float v = x[(size_t)r * HD + col];
        s += v; q += v * v;
    }
    atomicAdd(&sums[col], s);
    atomicAdd(&sums[HD + col], q);
}
__global__ void k_bn_final(const float* __restrict__ sums, const float* __restrict__ g,
                           const float* __restrict__ b, float* __restrict__ sc, float* __restrict__ sh) {
    int c = threadIdx.x;
    float mu  = sums[c] * (1.0f / NN);
    float var = sums[HD + c] * (1.0f / NN) - mu * mu;
    float rstd = rsqrtf(var + BNEPS);
    float s = g[c] * rstd;
    sc[c] = s;
    sh[c] = b[c] - mu * s;
}
// activation split: [NN,256] fp32 -> [NPAD,256] bf16 hi/lo, optional per-row scale
template <bool SC>
__global__ void k_splitA(const float4* __restrict__ src, uint2* __restrict__ hi,
                         uint2* __restrict__ lo, const float* __restrict__ rs) {
    int i = blockIdx.x * blockDim.x + threadIdx.x;
    if (i >= NPAD * 64) return;
    int row = i >> 6;
    float4 f = make_float4(0.f, 0.f, 0.f, 0.f);
    if (row < NN) {
        f = src[i];
        if (SC) { float s = rs[row]; f.x *= s; f.y *= s; f.z *= s; f.w *= s; }
    }
    uint2 h, l;
    split4(f, h, l);
    hi[i] = h; lo[i] = l;
}
__global__ void k_splitW(const float4* __restrict__ src, uint2* __restrict__ hi,
                         uint2* __restrict__ lo, int n4) {
    int i = blockIdx.x * blockDim.x + threadIdx.x;
    if (i >= n4) return;
    uint2 h, l;
    split4(src[i], h, l);
    hi[i] = h; lo[i] = l;
}

// ---------------- HMMA (mma.sync) GEMM: C[M,Nc] = A@W^T (+A2@W2^T) + bias --------
// bf16x3 split, tile 128x128, BK=32, 8 warps (warp tile 64x32), cp.async 2-stage.
// EPI 0: relu; 1: none; 2: + relu(aux*bn_sc + bn_sh). ch/cl: optional bf16 planes of C.
#define SM_ALO 10240
#define SM_WHI 20480
#define SM_WLO 30720
#define STAGE  40960
#define SMEMSZ (2 * STAGE)

__device__ __forceinline__ void mg_issue(
    uint32_t sbase, int tid, int m0, int n0, int K, int k0,
    const __nv_bfloat16* pah, const __nv_bfloat16* pal,
    const __nv_bfloat16* pwh, const __nv_bfloat16* pwl) {
#pragma unroll
    for (int c = 0; c < 2; c++) {
        int i = tid + c * 256;
        int row = i >> 2, c16 = i & 3;
        uint32_t soff = (uint32_t)(row * 80 + c16 * 16);
        size_t ga = (size_t)(m0 + row) * K + k0 + c16 * 8;
        size_t gw = (size_t)(n0 + row) * K + k0 + c16 * 8;
        CP_ASYNC16(sbase + soff,          &pah[ga]);
        CP_ASYNC16(sbase + SM_ALO + soff, &pal[ga]);
        CP_ASYNC16(sbase + SM_WHI + soff, &pwh[gw]);
        CP_ASYNC16(sbase + SM_WLO + soff, &pwl[gw]);
    }
}

template <int EPI, bool DUAL>
__global__ void __launch_bounds__(256)
k_mgemm(const __nv_bfloat16* __restrict__ ah, const __nv_bfloat16* __restrict__ al,
        const __nv_bfloat16* __restrict__ wh, const __nv_bfloat16* __restrict__ wl,
        const __nv_bfloat16* __restrict__ a2h, const __nv_bfloat16* __restrict__ a2l,
        const __nv_bfloat16* __restrict__ w2h, const __nv_bfloat16* __restrict__ w2l,
        const float* __restrict__ bias,
        const float* __restrict__ bn_sc, const float* __restrict__ bn_sh,
        const float* __restrict__ aux,
        float* __restrict__ C,
        __nv_bfloat16* __restrict__ ch, __nv_bfloat16* __restrict__ cl,
        int M, int Nc, int K) {
    extern __shared__ char smem[];
    uint32_t sb = smem_u32(smem);
    const int tid  = threadIdx.x;
    const int lane = tid & 31;
    const int wid  = tid >> 5;
    const int wm   = wid & 1;      // 2 warp-rows of 64
    const int wn   = wid >> 1;     // 4 warp-cols of 32
    const int m0 = blockIdx.y * 128;
    const int n0 = blockIdx.x * 128;

    const int cpp = K / 32;
    const int nit = (DUAL ? 2 : 1) * cpp;

    float acc[4][4][4];
#pragma unroll
    for (int a = 0; a < 4; a++)
#pragma unroll
        for (int b = 0; b < 4; b++)
#pragma unroll
            for (int c = 0; c < 4; c++) acc[a][b][c] = 0.f;

    // prologue: stage 0
    {
        mg_issue(sb, tid, m0, n0, K, 0, ah, al, wh, wl);
        CP_COMMIT();
    }

    for (int it = 0; it < nit; it++) {
        if (it + 1 < nit) {
            int pass = DUAL ? ((it + 1) >= cpp ? 1 : 0) : 0;
            int k0 = ((it + 1) - pass * cpp) * 32;
            mg_issue(sb + ((it + 1) & 1) * STAGE, tid, m0, n0, K, k0,
                     pass ? a2h : ah, pass ? a2l : al, pass ? w2h : wh, pass ? w2l : wl);
            CP_COMMIT();
            CP_WAIT(1);
        } else {
            CP_WAIT(0);
        }
        __syncthreads();

        uint32_t sA = sb + (it & 1) * STAGE;
#pragma unroll
        for (int ks = 0; ks < 2; ks++) {
            uint32_t ahf[4][4], alf[4][4];
#pragma unroll
            for (int mi = 0; mi < 4; mi++) {
                uint32_t ad = sA + (uint32_t)((wm * 64 + mi * 16 + (lane & 15)) * 80 +
                                              (ks * 16 + (lane >> 4) * 8) * 2);
                LDMATRIX_X4(ahf[mi][0], ahf[mi][1], ahf[mi][2], ahf[mi][3], ad);
                LDMATRIX_X4(alf[mi][0], alf[mi][1], alf[mi][2], alf[mi][3], ad + SM_ALO);
            }
            uint32_t bhf[4][2], blf[4][2];
#pragma unroll
            for (int nf2 = 0; nf2 < 2; nf2++) {
                int t = lane >> 3;
                uint32_t ad = sA + SM_WHI +
                    (uint32_t)((wn * 32 + nf2 * 16 + (t >> 1) * 8 + (lane & 7)) * 80 +
                               (ks * 16 + (t & 1) * 8) * 2);
                uint32_t r0, r1, r2, r3;
                LDMATRIX_X4(r0, r1, r2, r3, ad);
                bhf[nf2 * 2][0] = r0; bhf[nf2 * 2][1] = r1;
                bhf[nf2 * 2 + 1][0] = r2; bhf[nf2 * 2 + 1][1] = r3;
                LDMATRIX_X4(r0, r1, r2, r3, ad + (SM_WLO - SM_WHI));
                blf[nf2 * 2][0] = r0; blf[nf2 * 2][1] = r1;
                blf[nf2 * 2 + 1][0] = r2; blf[nf2 * 2 + 1][1] = r3;
            }
#pragma unroll
            for (int mi = 0; mi < 4; mi++)
#pragma unroll
                for (int ni = 0; ni < 4; ni++) MMA_BF16(acc[mi][ni], ahf[mi], bhf[ni]);
#pragma unroll
            for (int mi = 0; mi < 4; mi++)
#pragma unroll
                for (int ni = 0; ni < 4; ni++) MMA_BF16(acc[mi][ni], ahf[mi], blf[ni]);
#pragma unroll
            for (int mi = 0; mi < 4; mi++)
#pragma unroll
                for (int ni = 0; ni < 4; ni++) MMA_BF16(acc[mi][ni], alf[mi], bhf[ni]);
        }
        __syncthreads();
    }

    // epilogue
    const int r = lane >> 2, cq = lane & 3;
#pragma unroll
    for (int mi = 0; mi < 4; mi++) {
#pragma unroll
        for (int hrow = 0; hrow < 2; hrow++) {
            int m = m0 + wm * 64 + mi * 16 + r + hrow * 8;
            if (m >= M) continue;
#pragma unroll
            for (int ni = 0; ni < 4; ni++) {
                int n = n0 + wn * 32 + ni * 8 + cq * 2;
                float2 v = make_float2(acc[mi][ni][hrow * 2], acc[mi][ni][hrow * 2 + 1]);
                v.x += bias[n]; v.y += bias[n + 1];
                if (EPI == 0) { v.x = fmaxf(v.x, 0.f); v.y = fmaxf(v.y, 0.f); }
                if (EPI == 2) {
                    float2 ax = *(const float2*)&aux[(size_t)m * Nc + n];
                    v.x += fmaxf(fmaf(ax.x, bn_sc[n],     bn_sh[n]),     0.f);
                    v.y += fmaxf(fmaf(ax.y, bn_sc[n + 1], bn_sh[n + 1]), 0.f);
                }
                *(float2*)&C[(size_t)m * Nc + n] = v;
                if (ch) {
                    uint32_t hh, ll;
                    split2(v, hh, ll);
                    *(uint32_t*)&ch[(size_t)m * Nc + n] = hh;
                    *(uint32_t*)&cl[(size_t)m * Nc + n] = ll;
                }
            }
        }
    }
}

// ---------------- final head ----------------
__global__ void k_out_lsm(const float* __restrict__ h, const float* __restrict__ w,
                          const float* __restrict__ b, float* __restrict__ out, int M) {
    int row = blockIdx.x * blockDim.y + threadIdx.y;
    if (row >= M) return;
    int lane = threadIdx.x;
    const float* hr = h + (size_t)row * HD;
    float s0 = 0.f, s1 = 0.f;
    for (int k = lane; k < HD; k += 32) {
        float v = hr[k];
        s0 = fmaf(v, w[k], s0);
        s1 = fmaf(v, w[HD + k], s1);
    }
#pragma unroll
    for (int o = 16; o; o >>= 1) {
        s0 += __shfl_down_sync(0xffffffffu, s0, o);
        s1 += __shfl_down_sync(0xffffffffu, s1, o);
    }
    if (lane == 0) {
        float z0 = s0 + b[0], z1 = s1 + b[1];
        float mx = fmaxf(z0, z1);
        float lse = mx + logf(expf(z0 - mx) + expf(z1 - mx));
        out[(size_t)row * 2 + 0] = z0 - lse;
        out[(size_t)row * 2 + 1] = z1 - lse;
    }
}

// ---------------- launch ----------------
extern "C" void kernel_launch(void* const* d_in, const int* in_sizes, int n_in,
                              void* d_out, int out_size) {
    const float* x    = (const float*)d_in[0];
    const int*   ei   = (const int*)  d_in[1];
    const float* in_w = (const float*)d_in[2];
    const float* in_b = (const float*)d_in[3];
    const float* cwl  = (const float*)d_in[4];
    const float* cbl  = (const float*)d_in[5];
    const float* cwr  = (const float*)d_in[6];
    const float* bng  = (const float*)d_in[7];
    const float* bnb  = (const float*)d_in[8];
    const float* skw  = (const float*)d_in[9];
    const float* skb  = (const float*)d_in[10];
    const float* mw1  = (const float*)d_in[11];
    const float* mb1  = (const float*)d_in[12];
    const float* mw2  = (const float*)d_in[13];
    const float* mb2  = (const float*)d_in[14];
    const float* outw = (const float*)d_in[15];
    const float* outb = (const float*)d_in[16];
    float* out = (float*)d_out;

    const int* src = ei;
    const int* dst = ei + EE;

    float *b0, *b1, *b2, *bt, *deg, *bns, *bsc, *bsh;
    cudaGetSymbolAddress((void**)&b0,  g_buf0);
    cudaGetSymbolAddress((void**)&b1,  g_buf1);
    cudaGetSymbolAddress((void**)&b2,  g_buf2);
    cudaGetSymbolAddress((void**)&bt,  g_mlp);
    cudaGetSymbolAddress((void**)&deg, g_deg);
    cudaGetSymbolAddress((void**)&bns, g_bnsum);
    cudaGetSymbolAddress((void**)&bsc, g_bnsc);
    cudaGetSymbolAddress((void**)&bsh, g_bnsh);
    __nv_bfloat16 *p0h, *p0l, *p1h, *p1l, *bth, *btl, *wph, *wpl;
    cudaGetSymbolAddress((void**)&p0h, g_p0h);
    cudaGetSymbolAddress((void**)&p0l, g_p0l);
    cudaGetSymbolAddress((void**)&p1h, g_p1h);
    cudaGetSymbolAddress((void**)&p1l, g_p1l);
    cudaGetSymbolAddress((void**)&bth, g_bth);
    cudaGetSymbolAddress((void**)&btl, g_btl);
    cudaGetSymbolAddress((void**)&wph, g_wph);
    cudaGetSymbolAddress((void**)&wpl, g_wpl);

    cudaFuncSetAttribute(k_mgemm<0, false>, cudaFuncAttributeMaxDynamicSharedMemorySize, SMEMSZ);
    cudaFuncSetAttribute(k_mgemm<1, true >, cudaFuncAttributeMaxDynamicSharedMemorySize, SMEMSZ);
    cudaFuncSetAttribute(k_mgemm<2, false>, cudaFuncAttributeMaxDynamicSharedMemorySize, SMEMSZ);
    cudaFuncSetAttribute(k_mgemm<1, false>, cudaFuncAttributeMaxDynamicSharedMemorySize, SMEMSZ);

    const int TPB = 256;
    const long long feat4 = (long long)NN * 64;
    const int featBlocks = (int)((feat4 + TPB - 1) / TPB);
    const long long scat = (long long)EE * 64;
    const int scatBlocks = (int)((scat + TPB - 1) / TPB);
    const int bnChunks = (NN + 127) / 128;
    const int splBlocks = (NPAD * 64 + TPB - 1) / TPB;

    // degrees -> inverse degrees
    k_zero4<<<(NN / 4 + TPB - 1) / TPB, TPB>>>((float4*)deg, NN / 4);
    k_deg_count<<<(EE + TPB - 1) / TPB, TPB>>>(dst, deg, EE);
    k_deg_inv<<<(NN + TPB - 1) / TPB, TPB>>>(deg, NN);

    // split all weights into bf16 planes
    k_splitW<<<(16384 + TPB - 1) / TPB, TPB>>>((const float4*)in_w, (uint2*)(wph + WOFF_IN),  (uint2*)(wpl + WOFF_IN),  16384);
    k_splitW<<<(65536 + TPB - 1) / TPB, TPB>>>((const float4*)cwl,  (uint2*)(wph + WOFF_CWL), (uint2*)(wpl + WOFF_CWL), 65536);
    k_splitW<<<(65536 + TPB - 1) / TPB, TPB>>>((const float4*)cwr,  (uint2*)(wph + WOFF_CWR), (uint2*)(wpl + WOFF_CWR), 65536);
    k_splitW<<<(65536 + TPB - 1) / TPB, TPB>>>((const float4*)skw,  (uint2*)(wph + WOFF_SKW), (uint2*)(wpl + WOFF_SKW), 65536);
    k_splitW<<<(32768 + TPB - 1) / TPB, TPB>>>((const float4*)mw1,  (uint2*)(wph + WOFF_MW1), (uint2*)(wpl + WOFF_MW1), 32768);
    k_splitW<<<(32768 + TPB - 1) / TPB, TPB>>>((const float4*)mw2,  (uint2*)(wph + WOFF_MW2), (uint2*)(wpl + WOFF_MW2), 32768);

    dim3 gg(HD / 128, NPAD / 128);   // (2, 391)
    dim3 gg2(H2 / 128, NPAD / 128);  // (4, 391)

    // split x -> set0 ; in-proj + relu -> b0 fp32, planes set1
    k_splitA<false><<<splBlocks, TPB>>>((const float4*)x, (uint2*)p0h, (uint2*)p0l, nullptr);
    k_mgemm<0, false><<<gg, TPB, SMEMSZ>>>(p0h, p0l, wph + WOFF_IN, wpl + WOFF_IN,
                                           nullptr, nullptr, nullptr, nullptr,
                                           in_b, nullptr, nullptr, nullptr,
                                           b0, p1h, p1l, NN, HD, HD);

    float* bufs[3] = {b0, b1, b2};
    __nv_bfloat16* seth[2] = {p0h, p1h};
    __nv_bfloat16* setl[2] = {p0l, p1l};
    int hi = 0;
    for (int l = 0; l < LL; l++) {
        float* h   = bufs[hi];
        float* agg = bufs[(hi + 1) % 3];
        float* cv  = bufs[(hi + 2) % 3];
        __nv_bfloat16 *shh = seth[(l + 1) & 1], *shl = setl[(l + 1) & 1];  // h planes
        __nv_bfloat16 *soh = seth[l & 1],       *sol = setl[l & 1];        // agg, then next-h planes

        k_zero4<<<featBlocks, TPB>>>((float4*)agg, (int)feat4);
        k_scatter<<<scatBlocks, TPB>>>((const float4*)h, src, dst, agg);
        // agg planes with degree normalization fused
        k_splitA<true><<<splBlocks, TPB>>>((const float4*)agg, (uint2*)soh, (uint2*)sol, deg);

        // cv = (agg/deg) @ wl^T + h @ wr^T + bl
        k_mgemm<1, true><<<gg, TPB, SMEMSZ>>>(soh, sol, wph + WOFF_CWL + (size_t)l * 65536, wpl + WOFF_CWL + (size_t)l * 65536,
                                              shh, shl, wph + WOFF_CWR + (size_t)l * 65536, wpl + WOFF_CWR + (size_t)l * 65536,
                                              cbl + (size_t)l * HD, nullptr, nullptr, nullptr,
                                              cv, nullptr, nullptr, NN, HD, HD);

        // batch-norm statistics on cv
        k_zero4<<<1, 128>>>((float4*)bns, 128);
        k_bn_reduce<<<bnChunks, HD>>>(cv, bns);
        k_bn_final<<<1, HD>>>(bns, bng + (size_t)l * HD, bnb + (size_t)l * HD, bsc, bsh);

        // cv = h @ skip_w^T + skip_b + relu(bn(cv)); next-h planes -> so (agg planes dead)
        k_mgemm<2, false><<<gg, TPB, SMEMSZ>>>(shh, shl, wph + WOFF_SKW + (size_t)l * 65536, wpl + WOFF_SKW + (size_t)l * 65536,
                                               nullptr, nullptr, nullptr, nullptr,
                                               skb + (size_t)l * HD, bsc, bsh, cv,
                                               cv, soh, sol, NN, HD, HD);
        hi = (hi + 2) % 3;
    }

    __nv_bfloat16 *fhh = seth[(LL - 1) & 1], *fhl = setl[(LL - 1) & 1];
    float* h2 = bufs[(hi + 1) % 3];

    // MLP1: relu(h @ mw1^T + mb1) -> g_mlp fp32, planes bth/btl (Nc=512)
    k_mgemm<0, false><<<gg2, TPB, SMEMSZ>>>(fhh, fhl, wph + WOFF_MW1, wpl + WOFF_MW1,
                                            nullptr, nullptr, nullptr, nullptr,
                                            mb1, nullptr, nullptr, nullptr,
                                            bt, bth, btl, NN, H2, HD);
    // MLP2: bt @ mw2^T + mb2 -> h2 (K=512)
    k_mgemm<1, false><<<gg, TPB, SMEMSZ>>>(bth, btl, wph + WOFF_MW2, wpl + WOFF_MW2,
                                           nullptr, nullptr, nullptr, nullptr,
                                           mb2, nullptr, nullptr, nullptr,
                                           h2, nullptr, nullptr, NN, HD, H2);

    // output head + log_softmax
    dim3 ob(32, 8);
    k_out_lsm<<<(NN + 7) / 8, ob>>>(h2, outw, outb, out, NN);
}

// round 12
// speedup vs baseline: 2.4819x; 1.3549x over previous
#include <cuda_runtime.h>
#include <cuda_bf16.h>
#include <math.h>
#include <stdint.h>

#define NN   50000
#define EE   800000
#define HD   256
#define LL   4
#define H2   512
#define BNEPS 1e-5f
#define NPAD 50048   // 391*128
#define SCAN_B 1024
#define NBLK   49    // ceil(NN/SCAN_B)

// ---------------- scratch (no allocations allowed) ----------------
__device__ float g_cv [(size_t)NN * HD];     // conv output (BN aux)
__device__ float g_h2 [(size_t)NN * HD];     // MLP2 output
__device__ float g_bnsum[2 * HD];
__device__ float g_bnsc [HD];
__device__ float g_bnsh [HD];

// CSR
__device__ int g_cnt [NN + SCAN_B];          // counts -> inclusive scan (in-place)
__device__ int g_bsum[64];
__device__ int g_rowptr[NN + 4];
__device__ int g_fill[NN + 16];
__device__ int g_eidx[EE];

// bf16 hi/lo activation planes (pad rows stay zero: zero-init, never written)
__device__ __align__(16) __nv_bfloat16 g_p0h[(size_t)NPAD * HD];
__device__ __align__(16) __nv_bfloat16 g_p0l[(size_t)NPAD * HD];
__device__ __align__(16) __nv_bfloat16 g_p1h[(size_t)NPAD * HD];
__device__ __align__(16) __nv_bfloat16 g_p1l[(size_t)NPAD * HD];
__device__ __align__(16) __nv_bfloat16 g_bth[(size_t)NPAD * H2];
__device__ __align__(16) __nv_bfloat16 g_btl[(size_t)NPAD * H2];

// weight planes, concatenated
#define WOFF_IN  0
#define WOFF_CWL 65536
#define WOFF_CWR 327680
#define WOFF_SKW 589824
#define WOFF_MW1 851968
#define WOFF_MW2 983040
#define WTOT     1114112
__device__ __align__(16) __nv_bfloat16 g_wph[WTOT];
__device__ __align__(16) __nv_bfloat16 g_wpl[WTOT];

// ---------------- PTX helpers ----------------
__device__ __forceinline__ uint32_t smem_u32(const void* p) {
    uint32_t a;
    asm("{ .reg .u64 t; cvta.to.shared.u64 t, %1; cvt.u32.u64 %0, t; }" : "=r"(a) : "l"(p));
    return a;
}
#define CP_ASYNC16(s, g) \
    asm volatile("cp.async.cg.shared.global [%0], [%1], 16;" :: "r"(s), "l"(g) : "memory")
#define CP_COMMIT() asm volatile("cp.async.commit_group;" ::: "memory")
#define CP_WAIT(N)  asm volatile("cp.async.wait_group %0;" :: "n"(N) : "memory")

#define LDMATRIX_X4(r0, r1, r2, r3, a) \
    asm volatile("ldmatrix.sync.aligned.m8n8.x4.shared.b16 {%0,%1,%2,%3}, [%4];" \
                 : "=r"(r0), "=r"(r1), "=r"(r2), "=r"(r3) : "r"(a))

#define MMA_BF16(c, a, b) \
    asm volatile("mma.sync.aligned.m16n8k16.row.col.f32.bf16.bf16.f32 " \
                 "{%0,%1,%2,%3}, {%4,%5,%6,%7}, {%8,%9}, {%0,%1,%2,%3};" \
                 : "+f"((c)[0]), "+f"((c)[1]), "+f"((c)[2]), "+f"((c)[3]) \
                 : "r"((a)[0]), "r"((a)[1]), "r"((a)[2]), "r"((a)[3]), "r"((b)[0]), "r"((b)[1]))

// fp32 -> bf16 hi/lo (Dekker split; residual exact in fp32)
__device__ __forceinline__ void split4(float4 f, uint2& h, uint2& l) {
    asm("cvt.rn.bf16x2.f32 %0, %1, %2;" : "=r"(h.x) : "f"(f.y), "f"(f.x));
    asm("cvt.rn.bf16x2.f32 %0, %1, %2;" : "=r"(h.y) : "f"(f.w), "f"(f.z));
    float a0 = __uint_as_float(h.x << 16), a1 = __uint_as_float(h.x & 0xffff0000u);
    float a2 = __uint_as_float(h.y << 16), a3 = __uint_as_float(h.y & 0xffff0000u);
    float r0 = f.x - a0, r1 = f.y - a1, r2 = f.z - a2, r3 = f.w - a3;
    asm("cvt.rn.bf16x2.f32 %0, %1, %2;" : "=r"(l.x) : "f"(r1), "f"(r0));
    asm("cvt.rn.bf16x2.f32 %0, %1, %2;" : "=r"(l.y) : "f"(r3), "f"(r2));
}
__device__ __forceinline__ void split2(float2 f, uint32_t& h, uint32_t& l) {
    asm("cvt.rn.bf16x2.f32 %0, %1, %2;" : "=r"(h) : "f"(f.y), "f"(f.x));
    float a0 = __uint_as_float(h << 16), a1 = __uint_as_float(h & 0xffff0000u);
    float r0 = f.x - a0, r1 = f.y - a1;
    asm("cvt.rn.bf16x2.f32 %0, %1, %2;" : "=r"(l) : "f"(r1), "f"(r0));
}
__device__ __forceinline__ float bflo(uint32_t u) { return __uint_as_float(u << 16); }
__device__ __forceinline__ float bfhi(uint32_t u) { return __uint_as_float(u & 0xffff0000u); }

// ---------------- utility kernels ----------------
__global__ void k_zero4(float4* p, int n4) {
    int i = blockIdx.x * blockDim.x + threadIdx.x;
    if (i < n4) p[i] = make_float4(0.f, 0.f, 0.f, 0.f);
}
__global__ void k_count(const int* __restrict__ dst, int* __restrict__ cnt) {
    int i = blockIdx.x * blockDim.x + threadIdx.x;
    if (i < EE) atomicAdd(&cnt[dst[i]], 1);
}
// inclusive per-block scan, in-place; block sums out
__global__ void k_scan1(int* __restrict__ cnt, int* __restrict__ bsum) {
    __shared__ int s[SCAN_B];
    int b = blockIdx.x, t = threadIdx.x;
    int i = b * SCAN_B + t;
    s[t] = (i < NN) ? cnt[i] : 0;
    __syncthreads();
    for (int o = 1; o < SCAN_B; o <<= 1) {
        int x = (t >= o) ? s[t - o] : 0;
        __syncthreads();
        s[t] += x;
        __syncthreads();
    }
    if (i < NN) cnt[i] = s[t];
    if (t == SCAN_B - 1) bsum[b] = s[t];
}
__global__ void k_scan2(int* __restrict__ bsum) {
    __shared__ int s[64];
    int t = threadIdx.x;
    s[t] = (t < NBLK) ? bsum[t] : 0;
    __syncthreads();
    for (int o = 1; o < 64; o <<= 1) {
        int x = (t >= o) ? s[t - o] : 0;
        __syncthreads();
        s[t] += x;
        __syncthreads();
    }
    if (t < NBLK) bsum[t] = s[t];
}
__global__ void k_scan3(const int* __restrict__ cnt, const int* __restrict__ bsum,
                        int* __restrict__ rowptr) {
    int i = blockIdx.x * blockDim.x + threadIdx.x;
    if (i == 0) rowptr[0] = 0;
    if (i < NN) {
        int b = i / SCAN_B;
        rowptr[i + 1] = cnt[i] + (b > 0 ? bsum[b - 1] : 0);
    }
}
__global__ void k_fill(const int* __restrict__ src, const int* __restrict__ dst,
                       const int* __restrict__ rowptr, int* __restrict__ fill,
                       int* __restrict__ eidx) {
    int e = blockIdx.x * blockDim.x + threadIdx.x;
    if (e >= EE) return;
    int d = dst[e];
    int pos = rowptr[d] + atomicAdd(&fill[d], 1);
    eidx[pos] = src[e];
}

// CSR gather + mean + Dekker split: one warp per dst row, planes in, planes out
__global__ void __launch_bounds__(256) k_agg(
    const int* __restrict__ rowptr, const int* __restrict__ eidx,
    const uint4* __restrict__ hi, const uint4* __restrict__ lo,
    uint4* __restrict__ oh, uint4* __restrict__ ol) {
    int row = (blockIdx.x * 256 + threadIdx.x) >> 5;
    int lane = threadIdx.x & 31;
    if (row >= NN) return;
    int beg = rowptr[row], end = rowptr[row + 1];
    float acc[8];
#pragma unroll
    for (int q = 0; q < 8; q++) acc[q] = 0.f;
    for (int base = beg; base < end; base += 32) {
        int sidx = (base + lane < end) ? eidx[base + lane] : 0;
        int cnt = min(32, end - base);
        for (int j = 0; j < cnt; j++) {
            int s = __shfl_sync(0xffffffffu, sidx, j);
            uint4 h4 = hi[(size_t)s * 32 + lane];
            uint4 l4 = lo[(size_t)s * 32 + lane];
            acc[0] += bflo(h4.x) + bflo(l4.x);
            acc[1] += bfhi(h4.x) + bfhi(l4.x);
            acc[2] += bflo(h4.y) + bflo(l4.y);
            acc[3] += bfhi(h4.y) + bfhi(l4.y);
            acc[4] += bflo(h4.z) + bflo(l4.z);
            acc[5] += bfhi(h4.z) + bfhi(l4.z);
            acc[6] += bflo(h4.w) + bflo(l4.w);
            acc[7] += bfhi(h4.w) + bfhi(l4.w);
        }
    }
    float inv = 1.f / fmaxf((float)(end - beg), 1.f);
    uint32_t hh[4], ll[4];
#pragma unroll
    for (int q = 0; q < 4; q++)
        split2(make_float2(acc[2 * q] * inv, acc[2 * q + 1] * inv), hh[q], ll[q]);
    oh[(size_t)row * 32 + lane] = make_uint4(hh[0], hh[1], hh[2], hh[3]);
    ol[(size_t)row * 32 + lane] = make_uint4(ll[0], ll[1], ll[2], ll[3]);
}

__global__ void k_bn_reduce(const float* __restrict__ x, float* __restrict__ sums) {
    int col = threadIdx.x;
    int r0 = blockIdx.x * 128;
    int rend = min(r0 + 128, NN);
    float s = 0.f, q = 0.f;
    for (int r = r0; r < rend; r++) {
        float v = x[(size_t)r * HD + col];
        s += v; q += v * v;
    }
    atomicAdd(&sums[col], s);
    atomicAdd(&sums[HD + col], q);
}
__global__ void k_bn_final(const float* __restrict__ sums, const float* __restrict__ g,
                           const float* __restrict__ b, float* __restrict__ sc, float* __restrict__ sh) {
    int c = threadIdx.x;
    float mu  = sums[c] * (1.0f / NN);
    float var = sums[HD + c] * (1.0f / NN) - mu * mu;
    float rstd = rsqrtf(var + BNEPS);
    float s = g[c] * rstd;
    sc[c] = s;
    sh[c] = b[c] - mu * s;
}
// activation split for x: [NN,256] fp32 -> [NPAD,256] bf16 hi/lo (pad rows written zero)
__global__ void k_splitA(const float4* __restrict__ src, uint2* __restrict__ hi,
                         uint2* __restrict__ lo) {
    int i = blockIdx.x * blockDim.x + threadIdx.x;
    if (i >= NPAD * 64) return;
    int row = i >> 6;
    float4 f = make_float4(0.f, 0.f, 0.f, 0.f);
    if (row < NN) f = src[i];
    uint2 h, l;
    split4(f, h, l);
    hi[i] = h; lo[i] = l;
}
__global__ void k_splitW(const float4* __restrict__ src, uint2* __restrict__ hi,
                         uint2* __restrict__ lo, int n4) {
    int i = blockIdx.x * blockDim.x + threadIdx.x;
    if (i >= n4) return;
    uint2 h, l;
    split4(src[i], h, l);
    hi[i] = h; lo[i] = l;
}

// ---------------- HMMA (mma.sync) GEMM: C[M,Nc] = A@W^T (+A2@W2^T) + bias --------
// bf16x3 split, tile 128x128, BK=32, 8 warps (warp tile 64x32), cp.async 2-stage.
// EPI 0: relu; 1: none; 2: + relu(aux*bn_sc + bn_sh).
// C (fp32) and ch/cl (bf16 planes) are each optional (nullptr to skip).
#define SM_ALO 10240
#define SM_WHI 20480
#define SM_WLO 30720
#define STAGE  40960
#define SMEMSZ (2 * STAGE)

__device__ __forceinline__ void mg_issue(
    uint32_t sbase, int tid, int m0, int n0, int K, int k0,
    const __nv_bfloat16* pah, const __nv_bfloat16* pal,
    const __nv_bfloat16* pwh, const __nv_bfloat16* pwl) {
#pragma unroll
    for (int c = 0; c < 2; c++) {
        int i = tid + c * 256;
        int row = i >> 2, c16 = i & 3;
        uint32_t soff = (uint32_t)(row * 80 + c16 * 16);
        size_t ga = (size_t)(m0 + row) * K + k0 + c16 * 8;
        size_t gw = (size_t)(n0 + row) * K + k0 + c16 * 8;
        CP_ASYNC16(sbase + soff,          &pah[ga]);
        CP_ASYNC16(sbase + SM_ALO + soff, &pal[ga]);
        CP_ASYNC16(sbase + SM_WHI + soff, &pwh[gw]);
        CP_ASYNC16(sbase + SM_WLO + soff, &pwl[gw]);
    }
}

template <int EPI, bool DUAL>
__global__ void __launch_bounds__(256)
k_mgemm(const __nv_bfloat16* __restrict__ ah, const __nv_bfloat16* __restrict__ al,
        const __nv_bfloat16* __restrict__ wh, const __nv_bfloat16* __restrict__ wl,
        const __nv_bfloat16* __restrict__ a2h, const __nv_bfloat16* __restrict__ a2l,
        const __nv_bfloat16* __restrict__ w2h, const __nv_bfloat16* __restrict__ w2l,
        const float* __restrict__ bias,
        const float* __restrict__ bn_sc, const float* __restrict__ bn_sh,
        const float* __restrict__ aux,
        float* __restrict__ C,
        __nv_bfloat16* __restrict__ ch, __nv_bfloat16* __restrict__ cl,
        int M, int Nc, int K) {
    extern __shared__ char smem[];
    uint32_t sb = smem_u32(smem);
    const int tid  = threadIdx.x;
    const int lane = tid & 31;
    const int wid  = tid >> 5;
    const int wm   = wid & 1;
    const int wn   = wid >> 1;
    const int m0 = blockIdx.y * 128;
    const int n0 = blockIdx.x * 128;

    const int cpp = K / 32;
    const int nit = (DUAL ? 2 : 1) * cpp;

    float acc[4][4][4];
#pragma unroll
    for (int a = 0; a < 4; a++)
#pragma unroll
        for (int b = 0; b < 4; b++)
#pragma unroll
            for (int c = 0; c < 4; c++) acc[a][b][c] = 0.f;

    {
        mg_issue(sb, tid, m0, n0, K, 0, ah, al, wh, wl);
        CP_COMMIT();
    }

    for (int it = 0; it < nit; it++) {
        if (it + 1 < nit) {
            int pass = DUAL ? ((it + 1) >= cpp ? 1 : 0) : 0;
            int k0 = ((it + 1) - pass * cpp) * 32;
            mg_issue(sb + ((it + 1) & 1) * STAGE, tid, m0, n0, K, k0,
                     pass ? a2h : ah, pass ? a2l : al, pass ? w2h : wh, pass ? w2l : wl);
            CP_COMMIT();
            CP_WAIT(1);
        } else {
            CP_WAIT(0);
        }
        __syncthreads();

        uint32_t sA = sb + (it & 1) * STAGE;
#pragma unroll
        for (int ks = 0; ks < 2; ks++) {
            uint32_t ahf[4][4], alf[4][4];
#pragma unroll
            for (int mi = 0; mi < 4; mi++) {
                uint32_t ad = sA + (uint32_t)((wm * 64 + mi * 16 + (lane & 15)) * 80 +
                                              (ks * 16 + (lane >> 4) * 8) * 2);
                LDMATRIX_X4(ahf[mi][0], ahf[mi][1], ahf[mi][2], ahf[mi][3], ad);
                LDMATRIX_X4(alf[mi][0], alf[mi][1], alf[mi][2], alf[mi][3], ad + SM_ALO);
            }
            uint32_t bhf[4][2], blf[4][2];
#pragma unroll
            for (int nf2 = 0; nf2 < 2; nf2++) {
                int t = lane >> 3;
                uint32_t ad = sA + SM_WHI +
                    (uint32_t)((wn * 32 + nf2 * 16 + (t >> 1) * 8 + (lane & 7)) * 80 +
                               (ks * 16 + (t & 1) * 8) * 2);
                uint32_t r0, r1, r2, r3;
                LDMATRIX_X4(r0, r1, r2, r3, ad);
                bhf[nf2 * 2][0] = r0; bhf[nf2 * 2][1] = r1;
                bhf[nf2 * 2 + 1][0] = r2; bhf[nf2 * 2 + 1][1] = r3;
                LDMATRIX_X4(r0, r1, r2, r3, ad + (SM_WLO - SM_WHI));
                blf[nf2 * 2][0] = r0; blf[nf2 * 2][1] = r1;
                blf[nf2 * 2 + 1][0] = r2; blf[nf2 * 2 + 1][1] = r3;
            }
#pragma unroll
            for (int mi = 0; mi < 4; mi++)
#pragma unroll
                for (int ni = 0; ni < 4; ni++) MMA_BF16(acc[mi][ni], ahf[mi], bhf[ni]);
#pragma unroll
            for (int mi = 0; mi < 4; mi++)
#pragma unroll
                for (int ni = 0; ni < 4; ni++) MMA_BF16(acc[mi][ni], ahf[mi], blf[ni]);
#pragma unroll
            for (int mi = 0; mi < 4; mi++)
#pragma unroll
                for (int ni = 0; ni < 4; ni++) MMA_BF16(acc[mi][ni], alf[mi], bhf[ni]);
        }
        __syncthreads();
    }

    // epilogue
    const int r = lane >> 2, cq = lane & 3;
#pragma unroll
    for (int mi = 0; mi < 4; mi++) {
#pragma unroll
        for (int hrow = 0; hrow < 2; hrow++) {
            int m = m0 + wm * 64 + mi * 16 + r + hrow * 8;
            if (m >= M) continue;
#pragma unroll
            for (int ni = 0; ni < 4; ni++) {
                int n = n0 + wn * 32 + ni * 8 + cq * 2;
                float2 v = make_float2(acc[mi][ni][hrow * 2], acc[mi][ni][hrow * 2 + 1]);
                v.x += bias[n]; v.y += bias[n + 1];
                if (EPI == 0) { v.x = fmaxf(v.x, 0.f); v.y = fmaxf(v.y, 0.f); }
                if (EPI == 2) {
                    float2 ax = *(const float2*)&aux[(size_t)m * Nc + n];
                    v.x += fmaxf(fmaf(ax.x, bn_sc[n],     bn_sh[n]),     0.f);
                    v.y += fmaxf(fmaf(ax.y, bn_sc[n + 1], bn_sh[n + 1]), 0.f);
                }
                if (C) *(float2*)&C[(size_t)m * Nc + n] = v;
                if (ch) {
                    uint32_t hh, ll;
                    split2(v, hh, ll);
                    *(uint32_t*)&ch[(size_t)m * Nc + n] = hh;
                    *(uint32_t*)&cl[(size_t)m * Nc + n] = ll;
                }
            }
        }
    }
}

// ---------------- final head ----------------
__global__ void k_out_lsm(const float* __restrict__ h, const float* __restrict__ w,
                          const float* __restrict__ b, float* __restrict__ out, int M) {
    int row = blockIdx.x * blockDim.y + threadIdx.y;
    if (row >= M) return;
    int lane = threadIdx.x;
    const float* hr = h + (size_t)row * HD;
    float s0 = 0.f, s1 = 0.f;
    for (int k = lane; k < HD; k += 32) {
        float v = hr[k];
        s0 = fmaf(v, w[k], s0);
        s1 = fmaf(v, w[HD + k], s1);
    }
#pragma unroll
    for (int o = 16; o; o >>= 1) {
        s0 += __shfl_down_sync(0xffffffffu, s0, o);
        s1 += __shfl_down_sync(0xffffffffu, s1, o);
    }
    if (lane == 0) {
        float z0 = s0 + b[0], z1 = s1 + b[1];
        float mx = fmaxf(z0, z1);
        float lse = mx + logf(expf(z0 - mx) + expf(z1 - mx));
        out[(size_t)row * 2 + 0] = z0 - lse;
        out[(size_t)row * 2 + 1] = z1 - lse;
    }
}

// ---------------- launch ----------------
extern "C" void kernel_launch(void* const* d_in, const int* in_sizes, int n_in,
                              void* d_out, int out_size) {
    const float* x    = (const float*)d_in[0];
    const int*   ei   = (const int*)  d_in[1];
    const float* in_w = (const float*)d_in[2];
    const float* in_b = (const float*)d_in[3];
    const float* cwl  = (const float*)d_in[4];
    const float* cbl  = (const float*)d_in[5];
    const float* cwr  = (const float*)d_in[6];
    const float* bng  = (const float*)d_in[7];
    const float* bnb  = (const float*)d_in[8];
    const float* skw  = (const float*)d_in[9];
    const float* skb  = (const float*)d_in[10];
    const float* mw1  = (const float*)d_in[11];
    const float* mb1  = (const float*)d_in[12];
    const float* mw2  = (const float*)d_in[13];
    const float* mb2  = (const float*)d_in[14];
    const float* outw = (const float*)d_in[15];
    const float* outb = (const float*)d_in[16];
    float* out = (float*)d_out;

    const int* src = ei;
    const int* dst = ei + EE;

    float *cv, *h2, *bns, *bsc, *bsh;
    cudaGetSymbolAddress((void**)&cv,  g_cv);
    cudaGetSymbolAddress((void**)&h2,  g_h2);
    cudaGetSymbolAddress((void**)&bns, g_bnsum);
    cudaGetSymbolAddress((void**)&bsc, g_bnsc);
    cudaGetSymbolAddress((void**)&bsh, g_bnsh);
    int *cnt, *bsum, *rowptr, *fill, *eidx;
    cudaGetSymbolAddress((void**)&cnt,    g_cnt);
    cudaGetSymbolAddress((void**)&bsum,   g_bsum);
    cudaGetSymbolAddress((void**)&rowptr, g_rowptr);
    cudaGetSymbolAddress((void**)&fill,   g_fill);
    cudaGetSymbolAddress((void**)&eidx,   g_eidx);
    __nv_bfloat16 *p0h, *p0l, *p1h, *p1l, *bth, *btl, *wph, *wpl;
    cudaGetSymbolAddress((void**)&p0h, g_p0h);
    cudaGetSymbolAddress((void**)&p0l, g_p0l);
    cudaGetSymbolAddress((void**)&p1h, g_p1h);
    cudaGetSymbolAddress((void**)&p1l, g_p1l);
    cudaGetSymbolAddress((void**)&bth, g_bth);
    cudaGetSymbolAddress((void**)&btl, g_btl);
    cudaGetSymbolAddress((void**)&wph, g_wph);
    cudaGetSymbolAddress((void**)&wpl, g_wpl);

    cudaFuncSetAttribute(k_mgemm<0, false>, cudaFuncAttributeMaxDynamicSharedMemorySize, SMEMSZ);
    cudaFuncSetAttribute(k_mgemm<1, true >, cudaFuncAttributeMaxDynamicSharedMemorySize, SMEMSZ);
    cudaFuncSetAttribute(k_mgemm<2, false>, cudaFuncAttributeMaxDynamicSharedMemorySize, SMEMSZ);
    cudaFuncSetAttribute(k_mgemm<1, false>, cudaFuncAttributeMaxDynamicSharedMemorySize, SMEMSZ);

    const int TPB = 256;
    const int bnChunks = (NN + 127) / 128;
    const int splBlocks = (NPAD * 64 + TPB - 1) / TPB;
    const int eeBlocks = (EE + TPB - 1) / TPB;

    // ---- CSR build (once; reused all layers) ----
    k_zero4<<<((NN + SCAN_B) / 4 + TPB - 1) / TPB, TPB>>>((float4*)cnt, (NN + SCAN_B) / 4);
    k_zero4<<<((NN + 16) / 4 + TPB - 1) / TPB, TPB>>>((float4*)fill, (NN + 16) / 4);
    k_count<<<eeBlocks, TPB>>>(dst, cnt);
    k_scan1<<<NBLK, SCAN_B>>>(cnt, bsum);
    k_scan2<<<1, 64>>>(bsum);
    k_scan3<<<(NN + TPB - 1) / TPB, TPB>>>(cnt, bsum, rowptr);
    k_fill<<<eeBlocks, TPB>>>(src, dst, rowptr, fill, eidx);

    // ---- weight planes ----
    k_splitW<<<(16384 + TPB - 1) / TPB, TPB>>>((const float4*)in_w, (uint2*)(wph + WOFF_IN),  (uint2*)(wpl + WOFF_IN),  16384);
    k_splitW<<<(65536 + TPB - 1) / TPB, TPB>>>((const float4*)cwl,  (uint2*)(wph + WOFF_CWL), (uint2*)(wpl + WOFF_CWL), 65536);
    k_splitW<<<(65536 + TPB - 1) / TPB, TPB>>>((const float4*)cwr,  (uint2*)(wph + WOFF_CWR), (uint2*)(wpl + WOFF_CWR), 65536);
    k_splitW<<<(65536 + TPB - 1) / TPB, TPB>>>((const float4*)skw,  (uint2*)(wph + WOFF_SKW), (uint2*)(wpl + WOFF_SKW), 65536);
    k_splitW<<<(32768 + TPB - 1) / TPB, TPB>>>((const float4*)mw1,  (uint2*)(wph + WOFF_MW1), (uint2*)(wpl + WOFF_MW1), 32768);
    k_splitW<<<(32768 + TPB - 1) / TPB, TPB>>>((const float4*)mw2,  (uint2*)(wph + WOFF_MW2), (uint2*)(wpl + WOFF_MW2), 32768);

    dim3 gg(HD / 128, NPAD / 128);   // (2, 391)
    dim3 gg2(H2 / 128, NPAD / 128);  // (4, 391)
    const int aggBlocks = (NN * 32 + TPB - 1) / TPB;  // one warp per row

    // split x -> set0 ; in-proj + relu -> planes set1 (no fp32 out)
    k_splitA<<<splBlocks, TPB>>>((const float4*)x, (uint2*)p0h, (uint2*)p0l);
    k_mgemm<0, false><<<gg, TPB, SMEMSZ>>>(p0h, p0l, wph + WOFF_IN, wpl + WOFF_IN,
                                           nullptr, nullptr, nullptr, nullptr,
                                           in_b, nullptr, nullptr, nullptr,
                                           nullptr, p1h, p1l, NN, HD, HD);

    __nv_bfloat16* seth[2] = {p0h, p1h};
    __nv_bfloat16* setl[2] = {p0l, p1l};
    for (int l = 0; l < LL; l++) {
        __nv_bfloat16 *shh = seth[(l + 1) & 1], *shl = setl[(l + 1) & 1];  // h planes
        __nv_bfloat16 *soh = seth[l & 1],       *sol = setl[l & 1];        // agg, then next-h planes

        // agg planes = mean_{j->i} h_j  (CSR gather, deg fused)
        k_agg<<<aggBlocks, TPB>>>(rowptr, eidx, (const uint4*)shh, (const uint4*)shl,
                                  (uint4*)soh, (uint4*)sol);

        // cv = agg @ wl^T + h @ wr^T + bl  (fp32 out for BN/aux)
        k_mgemm<1, true><<<gg, TPB, SMEMSZ>>>(soh, sol, wph + WOFF_CWL + (size_t)l * 65536, wpl + WOFF_CWL + (size_t)l * 65536,
                                              shh, shl, wph + WOFF_CWR + (size_t)l * 65536, wpl + WOFF_CWR + (size_t)l * 65536,
                                              cbl + (size_t)l * HD, nullptr, nullptr, nullptr,
                                              cv, nullptr, nullptr, NN, HD, HD);

        // batch-norm statistics on cv
        k_zero4<<<1, 128>>>((float4*)bns, 128);
        k_bn_reduce<<<bnChunks, HD>>>(cv, bns);
        k_bn_final<<<1, HD>>>(bns, bng + (size_t)l * HD, bnb + (size_t)l * HD, bsc, bsh);

        // next h = h @ skip_w^T + skip_b + relu(bn(cv)); planes only -> so
        k_mgemm<2, false><<<gg, TPB, SMEMSZ>>>(shh, shl, wph + WOFF_SKW + (size_t)l * 65536, wpl + WOFF_SKW + (size_t)l * 65536,
                                               nullptr, nullptr, nullptr, nullptr,
                                               skb + (size_t)l * HD, bsc, bsh, cv,
                                               nullptr, soh, sol, NN, HD, HD);
    }

    __nv_bfloat16 *fhh = seth[(LL - 1) & 1], *fhl = setl[(LL - 1) & 1];

    // MLP1: relu(h @ mw1^T + mb1) -> planes bth/btl only (Nc=512)
    k_mgemm<0, false><<<gg2, TPB, SMEMSZ>>>(fhh, fhl, wph + WOFF_MW1, wpl + WOFF_MW1,
                                            nullptr, nullptr, nullptr, nullptr,
                                            mb1, nullptr, nullptr, nullptr,
                                            nullptr, bth, btl, NN, H2, HD);
    // MLP2: bt @ mw2^T + mb2 -> h2 fp32 (K=512)
    k_mgemm<1, false><<<gg, TPB, SMEMSZ>>>(bth, btl, wph + WOFF_MW2, wpl + WOFF_MW2,
                                           nullptr, nullptr, nullptr, nullptr,
                                           mb2, nullptr, nullptr, nullptr,
                                           h2, nullptr, nullptr, NN, HD, H2);

    // output head + log_softmax
    dim3 ob(32, 8);
    k_out_lsm<<<(NN + 7) / 8, ob>>>(h2, outw, outb, out, NN);
}